// round 6
// baseline (speedup 1.0000x reference)
#include <cuda_runtime.h>
#include <math.h>
#include <stdint.h>
#include <stddef.h>

#define NN 50000
#define EE 800000

// ---------------- scratch (static __device__, no allocation) ----------------
static __device__ int   g_is64;
static __device__ int   g_src[EE];       // edge order
static __device__ int   g_dst[EE];       // edge order
static __device__ int   g_pos[EE];       // edge id -> CSR slot
static __device__ int   g_srcc[EE];      // CSR order
static __device__ int   g_dstc[EE];      // CSR order
static __device__ int   g_deg[NN];
static __device__ int   g_off[NN + 1];
static __device__ int   g_cur[NN];
static __device__ float g_efA[(size_t)EE * 64];   // CSR order
static __device__ float g_efB[(size_t)EE * 64];   // CSR order
static __device__ float g_xsp[(size_t)NN * 64];
static __device__ float g_xdp[(size_t)NN * 64];
static __device__ float g_xv [(size_t)NN * 128];
static __device__ float g_ss [NN * 8];
static __device__ float g_sd [NN * 8];
static __device__ float g_h1 [(size_t)NN * 256];
static __device__ float g_h2 [(size_t)NN * 256];
static __device__ float g_xg [(size_t)NN * 320];
static __device__ float g_wae[64 * 8];

__device__ __forceinline__ float elu1(float x) { return x > 0.f ? x : expm1f(x); }
__device__ __forceinline__ float lrelu(float x) { return x > 0.f ? x : 0.2f * x; }

// ---------------- dtype detection + index conversion + degree zero ----------------
__global__ void detect_kernel(const int* __restrict__ a32) {
    __shared__ int any_nz;
    if (threadIdx.x == 0) any_nz = 0;
    __syncthreads();
    int nz = 0;
    for (int i = threadIdx.x; i < 4096; i += blockDim.x)
        nz |= (a32[2 * i + 1] != 0);
    if (nz) atomicOr(&any_nz, 1);
    __syncthreads();
    if (threadIdx.x == 0) g_is64 = (any_nz == 0) ? 1 : 0;
}

__global__ void zero_deg_kernel() {
    int i = blockIdx.x * blockDim.x + threadIdx.x;
    if (i < NN) g_deg[i] = 0;
}

__global__ void conv_idx_kernel(const int* __restrict__ a32) {
    int i = blockIdx.x * blockDim.x + threadIdx.x;
    if (i < EE) {
        if (g_is64) {
            g_src[i] = a32[2 * (size_t)i];
            g_dst[i] = a32[2 * (size_t)EE + 2 * (size_t)i];
        } else {
            g_src[i] = a32[i];
            g_dst[i] = a32[(size_t)EE + i];
        }
    }
}

// ---------------- CSR build ----------------
__global__ void count_kernel() {
    int i = blockIdx.x * blockDim.x + threadIdx.x;
    if (i < EE) atomicAdd(&g_deg[g_dst[i]], 1);
}

__global__ void scan_kernel() {
    __shared__ int s[1024];
    __shared__ int carry_s;
    int tid = threadIdx.x;
    if (tid == 0) carry_s = 0;
    __syncthreads();
    for (int base = 0; base < NN; base += 1024) {
        int v = (base + tid < NN) ? g_deg[base + tid] : 0;
        s[tid] = v;
        __syncthreads();
        for (int d = 1; d < 1024; d <<= 1) {
            int t = (tid >= d) ? s[tid - d] : 0;
            __syncthreads();
            s[tid] += t;
            __syncthreads();
        }
        int incl = s[tid];
        int carry = carry_s;
        if (base + tid < NN) {
            int ex = carry + incl - v;
            g_off[base + tid] = ex;
            g_cur[base + tid] = ex;
        }
        __syncthreads();
        if (tid == 1023) carry_s = carry + incl;
        __syncthreads();
    }
    if (tid == 0) g_off[NN] = carry_s;
}

__global__ void scatter_kernel() {
    int i = blockIdx.x * blockDim.x + threadIdx.x;
    if (i < EE) {
        int d = g_dst[i];
        int p = atomicAdd(&g_cur[d], 1);
        g_pos[i]  = p;
        g_srcc[p] = g_src[i];
        g_dstc[p] = d;
    }
}

// ---------------- tiled GEMM (C = A @ W), 128x64 tile, 4x8 microtile ----------
// mode 0: plain store.
// mode 1: edge MLP, rows are EDGE ids; out row = g_pos[r]; gathers g_src/g_dst.
// mode 2: edge MLP, rows are CSR slots; out row = r; gathers g_srcc/g_dstc.
__global__ __launch_bounds__(256) void gemm_kernel(
        const float* __restrict__ A, const float* __restrict__ W,
        float* __restrict__ C, int M, int K, int Cn, int mode,
        const float* __restrict__ bias) {
    __shared__ float As[16][132];   // [k][m], padded
    __shared__ float Bs[16][68];    // [k][n], padded
    int tid = threadIdx.x;          // 256
    int bm = blockIdx.x * 128;
    int bn = blockIdx.y * 64;
    int wid = tid >> 5, lane = tid & 31;
    int wm = (wid & 3) * 32, wn = (wid >> 2) * 32;
    int m_off = wm + (lane & 7) * 4;       // 4 rows
    int n_off = wn + (lane >> 3) * 8;      // 8 cols

    float acc[4][8];
#pragma unroll
    for (int i = 0; i < 4; i++)
#pragma unroll
        for (int j = 0; j < 8; j++) acc[i][j] = 0.f;

    for (int k0 = 0; k0 < K; k0 += 16) {
        // A tile: 128 rows x 16 k = 512 float4, transposed into As[k][m]
#pragma unroll
        for (int t = tid; t < 512; t += 256) {
            int row = t >> 2, seg = t & 3;
            float4 av = make_float4(0.f, 0.f, 0.f, 0.f);
            if (bm + row < M) av = *(const float4*)&A[(size_t)(bm + row) * K + k0 + seg * 4];
            As[seg * 4 + 0][row] = av.x;
            As[seg * 4 + 1][row] = av.y;
            As[seg * 4 + 2][row] = av.z;
            As[seg * 4 + 3][row] = av.w;
        }
        // B tile: 16 k x 64 n = 256 float4
        {
            int kk = tid >> 4, ns = tid & 15;
            float4 wv = *(const float4*)&W[(size_t)(k0 + kk) * Cn + bn + ns * 4];
            *(float4*)&Bs[kk][ns * 4] = wv;
        }
        __syncthreads();
#pragma unroll
        for (int k = 0; k < 16; ++k) {
            float4 a  = *(const float4*)&As[k][m_off];
            float4 b0 = *(const float4*)&Bs[k][n_off];
            float4 b1 = *(const float4*)&Bs[k][n_off + 4];
            float am[4] = {a.x, a.y, a.z, a.w};
            float bv[8] = {b0.x, b0.y, b0.z, b0.w, b1.x, b1.y, b1.z, b1.w};
#pragma unroll
            for (int i = 0; i < 4; i++)
#pragma unroll
                for (int j = 0; j < 8; j++)
                    acc[i][j] = fmaf(am[i], bv[j], acc[i][j]);
        }
        __syncthreads();
    }

    if (mode == 0) {
#pragma unroll
        for (int i = 0; i < 4; i++) {
            int r = bm + m_off + i;
            if (r < M) {
                float4 v0 = make_float4(acc[i][0], acc[i][1], acc[i][2], acc[i][3]);
                float4 v1 = make_float4(acc[i][4], acc[i][5], acc[i][6], acc[i][7]);
                *(float4*)&C[(size_t)r * Cn + bn + n_off]     = v0;
                *(float4*)&C[(size_t)r * Cn + bn + n_off + 4] = v1;
            }
        }
    } else {
        float4 bv0 = *(const float4*)&bias[n_off];
        float4 bv1 = *(const float4*)&bias[n_off + 4];
#pragma unroll
        for (int i = 0; i < 4; i++) {
            int r = bm + m_off + i;
            if (r < M) {
                int s, d, ro;
                if (mode == 1) { s = g_src[r];  d = g_dst[r];  ro = g_pos[r]; }
                else           { s = g_srcc[r]; d = g_dstc[r]; ro = r; }
                float4 a0 = *(const float4*)&g_xsp[(size_t)s * 64 + n_off];
                float4 a1 = *(const float4*)&g_xsp[(size_t)s * 64 + n_off + 4];
                float4 b0 = *(const float4*)&g_xdp[(size_t)d * 64 + n_off];
                float4 b1 = *(const float4*)&g_xdp[(size_t)d * 64 + n_off + 4];
                float4 v0, v1;
                v0.x = fmaxf(acc[i][0] + a0.x + b0.x + bv0.x, 0.f);
                v0.y = fmaxf(acc[i][1] + a0.y + b0.y + bv0.y, 0.f);
                v0.z = fmaxf(acc[i][2] + a0.z + b0.z + bv0.z, 0.f);
                v0.w = fmaxf(acc[i][3] + a0.w + b0.w + bv0.w, 0.f);
                v1.x = fmaxf(acc[i][4] + a1.x + b1.x + bv1.x, 0.f);
                v1.y = fmaxf(acc[i][5] + a1.y + b1.y + bv1.y, 0.f);
                v1.z = fmaxf(acc[i][6] + a1.z + b1.z + bv1.z, 0.f);
                v1.w = fmaxf(acc[i][7] + a1.w + b1.w + bv1.w, 0.f);
                *(float4*)&C[(size_t)ro * 64 + n_off]     = v0;
                *(float4*)&C[(size_t)ro * 64 + n_off + 4] = v1;
            }
        }
    }
}

// ---------------- per-node attention scalars: ss[n,h], sd[n,h] ----------------
__global__ void node_scalar_kernel(const float* __restrict__ xv, const float* __restrict__ a_s,
                                   const float* __restrict__ a_d, int D) {
    int idx = blockIdx.x * blockDim.x + threadIdx.x;
    if (idx >= NN * 8) return;
    int node = idx >> 3, h = idx & 7;
    const float* xr = xv + (size_t)node * 8 * D + h * D;
    const float* as = a_s + h * D;
    const float* ad = a_d + h * D;
    float s1 = 0.f, s2 = 0.f;
    for (int d = 0; d < D; ++d) {
        float v = xr[d];
        s1 = fmaf(v, as[d], s1);
        s2 = fmaf(v, ad[d], s2);
    }
    g_ss[idx] = s1;
    g_sd[idx] = s2;
}

// ---------------- wae[k,h] = sum_d cWe[k, h*16+d] * a_e[h,d] ----------------
__global__ void wae_kernel(const float* __restrict__ cWe, const float* __restrict__ a_e) {
    int idx = threadIdx.x;   // 512
    int k = idx >> 3, h = idx & 7;
    const float* w = cWe + k * 128 + h * 16;
    const float* a = a_e + h * 16;
    float s = 0.f;
#pragma unroll
    for (int d = 0; d < 16; ++d) s = fmaf(w[d], a[d], s);
    g_wae[k * 8 + h] = s;
}

// ---------------- EGAT per-dst-node kernel (warp per node, single pass) --------
__global__ __launch_bounds__(256) void egat_node_kernel(
        const float* __restrict__ xv, const float* __restrict__ efc,
        const float* __restrict__ cWe, float* __restrict__ hout) {
    int gwarp = (blockIdx.x * blockDim.x + threadIdx.x) >> 5;
    int lane = threadIdx.x & 31;
    if (gwarp >= NN) return;
    int n = gwarp;
    int beg = g_off[n], end = g_off[n + 1];

    int h2 = lane >> 2;            // head
    int kbase = (lane & 3) << 4;   // k-range [kbase, kbase+16)
    float sd2 = g_sd[n * 8 + h2];

    float wreg[16];
#pragma unroll
    for (int kk = 0; kk < 16; ++kk) wreg[kk] = g_wae[(kbase + kk) * 8 + h2];

    float sumex = 0.f;
    float av0 = 0.f, av1 = 0.f, av2 = 0.f, av3 = 0.f;
    float accT[16];
#pragma unroll
    for (int i = 0; i < 16; i++) accT[i] = 0.f;

#pragma unroll 2
    for (int i = beg; i < end; ++i) {
        int s = g_srcc[i];
        const float4* efr = (const float4*)&efc[(size_t)i * 64 + kbase];
        float4 e0 = efr[0], e1 = efr[1], e2 = efr[2], e3 = efr[3];
        float se = e0.x * wreg[0];
        se = fmaf(e0.y, wreg[1], se);  se = fmaf(e0.z, wreg[2], se);  se = fmaf(e0.w, wreg[3], se);
        se = fmaf(e1.x, wreg[4], se);  se = fmaf(e1.y, wreg[5], se);  se = fmaf(e1.z, wreg[6], se);
        se = fmaf(e1.w, wreg[7], se);  se = fmaf(e2.x, wreg[8], se);  se = fmaf(e2.y, wreg[9], se);
        se = fmaf(e2.z, wreg[10], se); se = fmaf(e2.w, wreg[11], se); se = fmaf(e3.x, wreg[12], se);
        se = fmaf(e3.y, wreg[13], se); se = fmaf(e3.z, wreg[14], se); se = fmaf(e3.w, wreg[15], se);
        se += __shfl_xor_sync(0xffffffffu, se, 1);
        se += __shfl_xor_sync(0xffffffffu, se, 2);

        float lg = lrelu(g_ss[s * 8 + h2] + sd2 + se);
        float ex = __expf(lg);
        sumex += ex;

        float4 xvv = *(const float4*)&xv[(size_t)s * 128 + (lane << 2)];
        av0 = fmaf(ex, xvv.x, av0);
        av1 = fmaf(ex, xvv.y, av1);
        av2 = fmaf(ex, xvv.z, av2);
        av3 = fmaf(ex, xvv.w, av3);
        accT[0]  = fmaf(ex, e0.x, accT[0]);  accT[1]  = fmaf(ex, e0.y, accT[1]);
        accT[2]  = fmaf(ex, e0.z, accT[2]);  accT[3]  = fmaf(ex, e0.w, accT[3]);
        accT[4]  = fmaf(ex, e1.x, accT[4]);  accT[5]  = fmaf(ex, e1.y, accT[5]);
        accT[6]  = fmaf(ex, e1.z, accT[6]);  accT[7]  = fmaf(ex, e1.w, accT[7]);
        accT[8]  = fmaf(ex, e2.x, accT[8]);  accT[9]  = fmaf(ex, e2.y, accT[9]);
        accT[10] = fmaf(ex, e2.z, accT[10]); accT[11] = fmaf(ex, e2.w, accT[11]);
        accT[12] = fmaf(ex, e3.x, accT[12]); accT[13] = fmaf(ex, e3.y, accT[13]);
        accT[14] = fmaf(ex, e3.z, accT[14]); accT[15] = fmaf(ex, e3.w, accT[15]);
    }

    float inv = 1.f / (sumex + 1e-16f);

    float4 ov;
    ov.x = elu1(av0 * inv); ov.y = elu1(av1 * inv);
    ov.z = elu1(av2 * inv); ov.w = elu1(av3 * inv);
    *(float4*)&hout[(size_t)n * 256 + (lane << 2)] = ov;

    float pd[16];
#pragma unroll
    for (int d = 0; d < 16; ++d) pd[d] = 0.f;
#pragma unroll
    for (int kk = 0; kk < 16; ++kk) {
        float t = accT[kk];
        const float* wr = &cWe[(size_t)(kbase + kk) * 128 + h2 * 16];
#pragma unroll
        for (int d = 0; d < 16; ++d) pd[d] = fmaf(t, wr[d], pd[d]);
    }
#pragma unroll
    for (int d = 0; d < 16; ++d) {
        pd[d] += __shfl_xor_sync(0xffffffffu, pd[d], 1);
        pd[d] += __shfl_xor_sync(0xffffffffu, pd[d], 2);
    }
    int sel = lane & 3;
    float o0, o1, o2, o3;
    if (sel == 0)      { o0 = pd[0];  o1 = pd[1];  o2 = pd[2];  o3 = pd[3]; }
    else if (sel == 1) { o0 = pd[4];  o1 = pd[5];  o2 = pd[6];  o3 = pd[7]; }
    else if (sel == 2) { o0 = pd[8];  o1 = pd[9];  o2 = pd[10]; o3 = pd[11]; }
    else               { o0 = pd[12]; o1 = pd[13]; o2 = pd[14]; o3 = pd[15]; }
    float4 on;
    on.x = elu1(o0 * inv); on.y = elu1(o1 * inv);
    on.z = elu1(o2 * inv); on.w = elu1(o3 * inv);
    *(float4*)&hout[(size_t)n * 256 + 128 + h2 * 16 + (sel << 2)] = on;
}

// ---------------- final GAT (concat=False -> mean over heads) ----------------
__global__ __launch_bounds__(256) void gat_node_kernel(
        const float* __restrict__ xg, const float* __restrict__ bias,
        float* __restrict__ out) {
    int gwarp = (blockIdx.x * blockDim.x + threadIdx.x) >> 5;
    int lane = threadIdx.x & 31;
    if (gwarp >= NN) return;
    int n = gwarp;
    int beg = g_off[n], end = g_off[n + 1];

    int h2 = lane >> 2;
    float sd2 = g_sd[n * 8 + h2];
    int c0 = (lane & 3) * 10;

    float acc[10];
#pragma unroll
    for (int j = 0; j < 10; j++) acc[j] = 0.f;
    float sumex = 0.f;

#pragma unroll 2
    for (int i = beg; i < end; ++i) {
        int s = g_srcc[i];
        float v = lrelu(g_ss[s * 8 + h2] + sd2);
        float ex = __expf(v);
        sumex += ex;
        const float* xr = &xg[(size_t)s * 320 + h2 * 40 + c0];
#pragma unroll
        for (int j = 0; j < 10; j += 2) {
            float2 t = *(const float2*)&xr[j];
            acc[j]     = fmaf(ex, t.x, acc[j]);
            acc[j + 1] = fmaf(ex, t.y, acc[j + 1]);
        }
    }
    float inv = 1.f / (sumex + 1e-16f);
#pragma unroll
    for (int j = 0; j < 10; ++j) {
        float v = acc[j] * inv;
        v += __shfl_xor_sync(0xffffffffu, v, 4);
        v += __shfl_xor_sync(0xffffffffu, v, 8);
        v += __shfl_xor_sync(0xffffffffu, v, 16);
        acc[j] = v;
    }
    if (lane < 4) {
#pragma unroll
        for (int j = 0; j < 10; ++j)
            out[(size_t)n * 40 + lane * 10 + j] = acc[j] * 0.125f + bias[lane * 10 + j];
    }
}

// ---------------- host ----------------
static inline dim3 ggrid(int M, int Cn) { return dim3((unsigned)((M + 127) / 128), (unsigned)(Cn / 64)); }

extern "C" void kernel_launch(void* const* d_in, const int* in_sizes, int n_in,
                              void* d_out, int out_size) {
    (void)in_sizes; (void)n_in; (void)out_size;
    const float* x     = (const float*)d_in[0];
    const int*   ei32  = (const int*)d_in[1];   // dtype decided on device (int32 vs int64)
    const float* ea    = (const float*)d_in[2];
    const float* e1_Ws = (const float*)d_in[3];
    const float* e1_Wd = (const float*)d_in[4];
    const float* e1_We = (const float*)d_in[5];
    const float* e1_b  = (const float*)d_in[6];
    const float* c1_Wv = (const float*)d_in[7];
    const float* c1_We = (const float*)d_in[8];
    const float* c1_as = (const float*)d_in[9];
    const float* c1_ad = (const float*)d_in[10];
    const float* c1_ae = (const float*)d_in[11];
    const float* e2_Ws = (const float*)d_in[12];
    const float* e2_Wd = (const float*)d_in[13];
    const float* e2_We = (const float*)d_in[14];
    const float* e2_b  = (const float*)d_in[15];
    const float* c2_Wv = (const float*)d_in[16];
    const float* c2_We = (const float*)d_in[17];
    const float* c2_as = (const float*)d_in[18];
    const float* c2_ad = (const float*)d_in[19];
    const float* c2_ae = (const float*)d_in[20];
    const float* g_Wp  = (const float*)d_in[21];
    const float* g_asP = (const float*)d_in[22];
    const float* g_adP = (const float*)d_in[23];
    const float* g_bP  = (const float*)d_in[24];
    float* out = (float*)d_out;

    void *p_efA, *p_efB, *p_xsp, *p_xdp, *p_xv, *p_h1, *p_h2, *p_xg;
    cudaGetSymbolAddress(&p_efA, g_efA);
    cudaGetSymbolAddress(&p_efB, g_efB);
    cudaGetSymbolAddress(&p_xsp, g_xsp);
    cudaGetSymbolAddress(&p_xdp, g_xdp);
    cudaGetSymbolAddress(&p_xv,  g_xv);
    cudaGetSymbolAddress(&p_h1,  g_h1);
    cudaGetSymbolAddress(&p_h2,  g_h2);
    cudaGetSymbolAddress(&p_xg,  g_xg);
    float* efA = (float*)p_efA; float* efB = (float*)p_efB;
    float* xsp = (float*)p_xsp; float* xdp = (float*)p_xdp;
    float* xv  = (float*)p_xv;  float* h1  = (float*)p_h1;
    float* h2  = (float*)p_h2;  float* xg  = (float*)p_xg;

    // CSR build (scatter deferred past the first GEMM so ncu -s 5 -c 1 captures a GEMM)
    detect_kernel<<<1, 1024>>>(ei32);                      // 1
    conv_idx_kernel<<<(EE + 255) / 256, 256>>>(ei32);      // 2
    zero_deg_kernel<<<(NN + 255) / 256, 256>>>();          // 3
    count_kernel<<<(EE + 255) / 256, 256>>>();             // 4
    scan_kernel<<<1, 1024>>>();                            // 5
    gemm_kernel<<<ggrid(NN, 64), 256>>>(x, e1_Ws, xsp, NN, 128, 64, 0, nullptr);  // 6 <- ncu
    gemm_kernel<<<ggrid(NN, 64), 256>>>(x, e1_Wd, xdp, NN, 128, 64, 0, nullptr);
    scatter_kernel<<<(EE + 255) / 256, 256>>>();
    gemm_kernel<<<ggrid(EE, 64), 256>>>(ea, e1_We, efA, EE, 16, 64, 1, e1_b);

    // ---- EGAT 1 ----
    gemm_kernel<<<ggrid(NN, 128), 256>>>(x, c1_Wv, xv, NN, 128, 128, 0, nullptr);
    node_scalar_kernel<<<(NN * 8 + 255) / 256, 256>>>(xv, c1_as, c1_ad, 16);
    wae_kernel<<<1, 512>>>(c1_We, c1_ae);
    egat_node_kernel<<<(NN + 7) / 8, 256>>>(xv, efA, c1_We, h1);

    // ---- layer 2: edge MLP (rows already CSR slots) ----
    gemm_kernel<<<ggrid(NN, 64), 256>>>(h1, e2_Ws, xsp, NN, 256, 64, 0, nullptr);
    gemm_kernel<<<ggrid(NN, 64), 256>>>(h1, e2_Wd, xdp, NN, 256, 64, 0, nullptr);
    gemm_kernel<<<ggrid(EE, 64), 256>>>(efA, e2_We, efB, EE, 64, 64, 2, e2_b);

    // ---- EGAT 2 ----
    gemm_kernel<<<ggrid(NN, 128), 256>>>(h1, c2_Wv, xv, NN, 256, 128, 0, nullptr);
    node_scalar_kernel<<<(NN * 8 + 255) / 256, 256>>>(xv, c2_as, c2_ad, 16);
    wae_kernel<<<1, 512>>>(c2_We, c2_ae);
    egat_node_kernel<<<(NN + 7) / 8, 256>>>(xv, efB, c2_We, h2);

    // ---- final GAT (mean over heads) ----
    gemm_kernel<<<ggrid(NN, 320), 256>>>(h2, g_Wp, xg, NN, 256, 320, 0, nullptr);
    node_scalar_kernel<<<(NN * 8 + 255) / 256, 256>>>(xg, g_asP, g_adP, 40);
    gat_node_kernel<<<(NN + 7) / 8, 256>>>(xg, g_bP, out);
}

// round 7
// speedup vs baseline: 1.0041x; 1.0041x over previous
#include <cuda_runtime.h>
#include <math.h>
#include <stdint.h>
#include <stddef.h>

#define NN 50000
#define EE 800000

// ---------------- scratch (static __device__, no allocation) ----------------
static __device__ int   g_src[EE];       // edge order
static __device__ int   g_dst[EE];       // edge order
static __device__ int   g_pos[EE];       // edge id -> CSR slot
static __device__ int   g_srcc[EE];      // CSR order
static __device__ int   g_dstc[EE];      // CSR order
static __device__ int   g_deg[NN];
static __device__ int   g_off[NN + 1];
static __device__ int   g_cur[NN];
static __device__ float g_efA[(size_t)EE * 64];   // CSR order
static __device__ float g_efB[(size_t)EE * 64];   // CSR order
static __device__ float g_xsp[(size_t)NN * 64];
static __device__ float g_xdp[(size_t)NN * 64];
static __device__ float g_xv [(size_t)NN * 128];
static __device__ float g_ss [NN * 8];
static __device__ float g_sd [NN * 8];
static __device__ float g_h1 [(size_t)NN * 256];
static __device__ float g_h2 [(size_t)NN * 256];
static __device__ float g_xg [(size_t)NN * 320];
static __device__ float g_wae[64 * 8];

__device__ __forceinline__ float elu1(float x) { return x > 0.f ? x : expm1f(x); }
__device__ __forceinline__ float lrelu(float x) { return x > 0.f ? x : 0.2f * x; }

// ---------------- prep: dtype detect (per-block, deterministic) + conv + zero ----
// int64 values < 2^31 have zero high words; sample the first 256 odd int32 slots.
// For int32 data these are random src values in [0,NN) — all-zero is impossible
// in practice. All blocks compute the same local verdict; no global flag needed.
__global__ void prep_kernel(const int* __restrict__ a32) {
    int tid = threadIdx.x;
    int nz = (tid < 256 && a32[2 * tid + 1] != 0) ? 1 : 0;
    int is64 = (__syncthreads_or(nz) == 0);
    int i = blockIdx.x * blockDim.x + tid;
    if (i < EE) {
        if (is64) {
            g_src[i] = a32[2 * (size_t)i];
            g_dst[i] = a32[2 * (size_t)EE + 2 * (size_t)i];
        } else {
            g_src[i] = a32[i];
            g_dst[i] = a32[(size_t)EE + i];
        }
    }
    if (i < NN) g_deg[i] = 0;
}

// ---------------- CSR build ----------------
__global__ void count_kernel() {
    int i = blockIdx.x * blockDim.x + threadIdx.x;
    if (i < EE) atomicAdd(&g_deg[g_dst[i]], 1);
}

__global__ void scan_kernel() {
    __shared__ int s[1024];
    __shared__ int carry_s;
    int tid = threadIdx.x;
    if (tid == 0) carry_s = 0;
    __syncthreads();
    for (int base = 0; base < NN; base += 1024) {
        int v = (base + tid < NN) ? g_deg[base + tid] : 0;
        s[tid] = v;
        __syncthreads();
        for (int d = 1; d < 1024; d <<= 1) {
            int t = (tid >= d) ? s[tid - d] : 0;
            __syncthreads();
            s[tid] += t;
            __syncthreads();
        }
        int incl = s[tid];
        int carry = carry_s;
        if (base + tid < NN) {
            int ex = carry + incl - v;
            g_off[base + tid] = ex;
            g_cur[base + tid] = ex;
        }
        __syncthreads();
        if (tid == 1023) carry_s = carry + incl;
        __syncthreads();
    }
    if (tid == 0) g_off[NN] = carry_s;
}

__global__ void scatter_kernel() {
    int i = blockIdx.x * blockDim.x + threadIdx.x;
    if (i < EE) {
        int d = g_dst[i];
        int p = atomicAdd(&g_cur[d], 1);
        g_pos[i]  = p;
        g_srcc[p] = g_src[i];
        g_dstc[p] = d;
    }
}

// ---------------- GEMM core: 128x64 tile, 4x8 microtile, 256 threads ----------
template <int MODE>
__device__ __forceinline__ void gemm_body(
        const float* __restrict__ A, const float* __restrict__ W,
        float* __restrict__ C, int M, int K, int Wld, int cof, int Cld,
        const float* __restrict__ bias, int bm) {
    __shared__ float As[16][132];
    __shared__ float Bs[16][68];
    int tid = threadIdx.x;
    int wid = tid >> 5, lane = tid & 31;
    int wm = (wid & 3) * 32, wn = (wid >> 2) * 32;
    int m_off = wm + (lane & 7) * 4;
    int n_off = wn + (lane >> 3) * 8;

    float acc[4][8];
#pragma unroll
    for (int i = 0; i < 4; i++)
#pragma unroll
        for (int j = 0; j < 8; j++) acc[i][j] = 0.f;

    for (int k0 = 0; k0 < K; k0 += 16) {
#pragma unroll
        for (int t = tid; t < 512; t += 256) {
            int row = t >> 2, seg = t & 3;
            float4 av = make_float4(0.f, 0.f, 0.f, 0.f);
            if (bm + row < M) av = *(const float4*)&A[(size_t)(bm + row) * K + k0 + seg * 4];
            As[seg * 4 + 0][row] = av.x;
            As[seg * 4 + 1][row] = av.y;
            As[seg * 4 + 2][row] = av.z;
            As[seg * 4 + 3][row] = av.w;
        }
        {
            int kk = tid >> 4, ns = tid & 15;
            float4 wv = *(const float4*)&W[(size_t)(k0 + kk) * Wld + cof + ns * 4];
            *(float4*)&Bs[kk][ns * 4] = wv;
        }
        __syncthreads();
#pragma unroll
        for (int k = 0; k < 16; ++k) {
            float4 a  = *(const float4*)&As[k][m_off];
            float4 b0 = *(const float4*)&Bs[k][n_off];
            float4 b1 = *(const float4*)&Bs[k][n_off + 4];
            float am[4] = {a.x, a.y, a.z, a.w};
            float bv[8] = {b0.x, b0.y, b0.z, b0.w, b1.x, b1.y, b1.z, b1.w};
#pragma unroll
            for (int i = 0; i < 4; i++)
#pragma unroll
                for (int j = 0; j < 8; j++)
                    acc[i][j] = fmaf(am[i], bv[j], acc[i][j]);
        }
        __syncthreads();
    }

    if (MODE == 0) {
#pragma unroll
        for (int i = 0; i < 4; i++) {
            int r = bm + m_off + i;
            if (r < M) {
                float4 v0 = make_float4(acc[i][0], acc[i][1], acc[i][2], acc[i][3]);
                float4 v1 = make_float4(acc[i][4], acc[i][5], acc[i][6], acc[i][7]);
                *(float4*)&C[(size_t)r * Cld + cof + n_off]     = v0;
                *(float4*)&C[(size_t)r * Cld + cof + n_off + 4] = v1;
            }
        }
    } else {
        float4 bv0 = *(const float4*)&bias[n_off];
        float4 bv1 = *(const float4*)&bias[n_off + 4];
#pragma unroll
        for (int i = 0; i < 4; i++) {
            int r = bm + m_off + i;
            if (r < M) {
                int s, d, ro;
                if (MODE == 1) { s = g_src[r];  d = g_dst[r];  ro = g_pos[r]; }
                else           { s = g_srcc[r]; d = g_dstc[r]; ro = r; }
                float4 a0 = *(const float4*)&g_xsp[(size_t)s * 64 + n_off];
                float4 a1 = *(const float4*)&g_xsp[(size_t)s * 64 + n_off + 4];
                float4 b0 = *(const float4*)&g_xdp[(size_t)d * 64 + n_off];
                float4 b1 = *(const float4*)&g_xdp[(size_t)d * 64 + n_off + 4];
                float4 v0, v1;
                v0.x = fmaxf(acc[i][0] + a0.x + b0.x + bv0.x, 0.f);
                v0.y = fmaxf(acc[i][1] + a0.y + b0.y + bv0.y, 0.f);
                v0.z = fmaxf(acc[i][2] + a0.z + b0.z + bv0.z, 0.f);
                v0.w = fmaxf(acc[i][3] + a0.w + b0.w + bv0.w, 0.f);
                v1.x = fmaxf(acc[i][4] + a1.x + b1.x + bv1.x, 0.f);
                v1.y = fmaxf(acc[i][5] + a1.y + b1.y + bv1.y, 0.f);
                v1.z = fmaxf(acc[i][6] + a1.z + b1.z + bv1.z, 0.f);
                v1.w = fmaxf(acc[i][7] + a1.w + b1.w + bv1.w, 0.f);
                *(float4*)&C[(size_t)ro * 64 + n_off]     = v0;
                *(float4*)&C[(size_t)ro * 64 + n_off + 4] = v1;
            }
        }
    }
}

// plain GEMM: mode 0 (store), 1 (edge-MLP via pos), 2 (edge-MLP CSR rows)
__global__ __launch_bounds__(256) void gemm_kernel(
        const float* __restrict__ A, const float* __restrict__ W,
        float* __restrict__ C, int M, int K, int Cn, int mode,
        const float* __restrict__ bias) {
    int bm = blockIdx.x * 128;
    int cof = blockIdx.y * 64;
    if (mode == 0)      gemm_body<0>(A, W, C, M, K, Cn, cof, Cn, bias, bm);
    else if (mode == 1) gemm_body<1>(A, W, C, M, K, Cn, cof, Cn, bias, bm);
    else                gemm_body<2>(A, W, C, M, K, Cn, cof, Cn, bias, bm);
}

// fused triple node GEMM: y=0 -> Ws->xsp, y=1 -> Wd->xdp, y=2,3 -> Wv->xv
__global__ __launch_bounds__(256) void gemm3_kernel(
        const float* __restrict__ A,
        const float* __restrict__ Ws, const float* __restrict__ Wd,
        const float* __restrict__ Wv, int M, int K) {
    int bm = blockIdx.x * 128;
    int y = blockIdx.y;
    if (y == 0)      gemm_body<0>(A, Ws, g_xsp, M, K, 64, 0, 64, nullptr, bm);
    else if (y == 1) gemm_body<0>(A, Wd, g_xdp, M, K, 64, 0, 64, nullptr, bm);
    else             gemm_body<0>(A, Wv, g_xv,  M, K, 128, (y - 2) * 64, 128, nullptr, bm);
}

// ---------------- node scalars (+ optional wae in last block) ----------------
__global__ void node_scalar_kernel(const float* __restrict__ xv, const float* __restrict__ a_s,
                                   const float* __restrict__ a_d, int D,
                                   const float* __restrict__ cWe, const float* __restrict__ a_e) {
    if (cWe && blockIdx.x == gridDim.x - 1) {
        // wae[k,h] = sum_d cWe[k, h*16+d] * a_e[h,d]   (512 entries, 256 threads)
        for (int j = threadIdx.x; j < 512; j += blockDim.x) {
            int k = j >> 3, h = j & 7;
            const float* w = cWe + k * 128 + h * 16;
            const float* a = a_e + h * 16;
            float s = 0.f;
#pragma unroll
            for (int d = 0; d < 16; ++d) s = fmaf(w[d], a[d], s);
            g_wae[j] = s;
        }
        return;
    }
    int idx = blockIdx.x * blockDim.x + threadIdx.x;
    if (idx >= NN * 8) return;
    int node = idx >> 3, h = idx & 7;
    const float* xr = xv + (size_t)node * 8 * D + h * D;
    const float* as = a_s + h * D;
    const float* ad = a_d + h * D;
    float s1 = 0.f, s2 = 0.f;
    for (int d = 0; d < D; ++d) {
        float v = xr[d];
        s1 = fmaf(v, as[d], s1);
        s2 = fmaf(v, ad[d], s2);
    }
    g_ss[idx] = s1;
    g_sd[idx] = s2;
}

// ---------------- EGAT per-dst-node kernel (warp per node, single pass) --------
__global__ __launch_bounds__(256) void egat_node_kernel(
        const float* __restrict__ xv, const float* __restrict__ efc,
        const float* __restrict__ cWe, float* __restrict__ hout) {
    int gwarp = (blockIdx.x * blockDim.x + threadIdx.x) >> 5;
    int lane = threadIdx.x & 31;
    if (gwarp >= NN) return;
    int n = gwarp;
    int beg = g_off[n], end = g_off[n + 1];

    int h2 = lane >> 2;            // head
    int kbase = (lane & 3) << 4;   // k-range [kbase, kbase+16)
    float sd2 = g_sd[n * 8 + h2];

    float wreg[16];
#pragma unroll
    for (int kk = 0; kk < 16; ++kk) wreg[kk] = g_wae[(kbase + kk) * 8 + h2];

    float sumex = 0.f;
    float av0 = 0.f, av1 = 0.f, av2 = 0.f, av3 = 0.f;
    float accT[16];
#pragma unroll
    for (int i = 0; i < 16; i++) accT[i] = 0.f;

#pragma unroll 2
    for (int i = beg; i < end; ++i) {
        int s = g_srcc[i];
        const float4* efr = (const float4*)&efc[(size_t)i * 64 + kbase];
        float4 e0 = efr[0], e1 = efr[1], e2 = efr[2], e3 = efr[3];
        float se = e0.x * wreg[0];
        se = fmaf(e0.y, wreg[1], se);  se = fmaf(e0.z, wreg[2], se);  se = fmaf(e0.w, wreg[3], se);
        se = fmaf(e1.x, wreg[4], se);  se = fmaf(e1.y, wreg[5], se);  se = fmaf(e1.z, wreg[6], se);
        se = fmaf(e1.w, wreg[7], se);  se = fmaf(e2.x, wreg[8], se);  se = fmaf(e2.y, wreg[9], se);
        se = fmaf(e2.z, wreg[10], se); se = fmaf(e2.w, wreg[11], se); se = fmaf(e3.x, wreg[12], se);
        se = fmaf(e3.y, wreg[13], se); se = fmaf(e3.z, wreg[14], se); se = fmaf(e3.w, wreg[15], se);
        se += __shfl_xor_sync(0xffffffffu, se, 1);
        se += __shfl_xor_sync(0xffffffffu, se, 2);

        float lg = lrelu(g_ss[s * 8 + h2] + sd2 + se);
        float ex = __expf(lg);
        sumex += ex;

        float4 xvv = *(const float4*)&xv[(size_t)s * 128 + (lane << 2)];
        av0 = fmaf(ex, xvv.x, av0);
        av1 = fmaf(ex, xvv.y, av1);
        av2 = fmaf(ex, xvv.z, av2);
        av3 = fmaf(ex, xvv.w, av3);
        accT[0]  = fmaf(ex, e0.x, accT[0]);  accT[1]  = fmaf(ex, e0.y, accT[1]);
        accT[2]  = fmaf(ex, e0.z, accT[2]);  accT[3]  = fmaf(ex, e0.w, accT[3]);
        accT[4]  = fmaf(ex, e1.x, accT[4]);  accT[5]  = fmaf(ex, e1.y, accT[5]);
        accT[6]  = fmaf(ex, e1.z, accT[6]);  accT[7]  = fmaf(ex, e1.w, accT[7]);
        accT[8]  = fmaf(ex, e2.x, accT[8]);  accT[9]  = fmaf(ex, e2.y, accT[9]);
        accT[10] = fmaf(ex, e2.z, accT[10]); accT[11] = fmaf(ex, e2.w, accT[11]);
        accT[12] = fmaf(ex, e3.x, accT[12]); accT[13] = fmaf(ex, e3.y, accT[13]);
        accT[14] = fmaf(ex, e3.z, accT[14]); accT[15] = fmaf(ex, e3.w, accT[15]);
    }

    float inv = 1.f / (sumex + 1e-16f);

    float4 ov;
    ov.x = elu1(av0 * inv); ov.y = elu1(av1 * inv);
    ov.z = elu1(av2 * inv); ov.w = elu1(av3 * inv);
    *(float4*)&hout[(size_t)n * 256 + (lane << 2)] = ov;

    float pd[16];
#pragma unroll
    for (int d = 0; d < 16; ++d) pd[d] = 0.f;
#pragma unroll
    for (int kk = 0; kk < 16; ++kk) {
        float t = accT[kk];
        const float* wr = &cWe[(size_t)(kbase + kk) * 128 + h2 * 16];
#pragma unroll
        for (int d = 0; d < 16; ++d) pd[d] = fmaf(t, wr[d], pd[d]);
    }
#pragma unroll
    for (int d = 0; d < 16; ++d) {
        pd[d] += __shfl_xor_sync(0xffffffffu, pd[d], 1);
        pd[d] += __shfl_xor_sync(0xffffffffu, pd[d], 2);
    }
    int sel = lane & 3;
    float o0, o1, o2, o3;
    if (sel == 0)      { o0 = pd[0];  o1 = pd[1];  o2 = pd[2];  o3 = pd[3]; }
    else if (sel == 1) { o0 = pd[4];  o1 = pd[5];  o2 = pd[6];  o3 = pd[7]; }
    else if (sel == 2) { o0 = pd[8];  o1 = pd[9];  o2 = pd[10]; o3 = pd[11]; }
    else               { o0 = pd[12]; o1 = pd[13]; o2 = pd[14]; o3 = pd[15]; }
    float4 on;
    on.x = elu1(o0 * inv); on.y = elu1(o1 * inv);
    on.z = elu1(o2 * inv); on.w = elu1(o3 * inv);
    *(float4*)&hout[(size_t)n * 256 + 128 + h2 * 16 + (sel << 2)] = on;
}

// ---------------- final GAT (concat=False -> mean over heads) ----------------
__global__ __launch_bounds__(256) void gat_node_kernel(
        const float* __restrict__ xg, const float* __restrict__ bias,
        float* __restrict__ out) {
    int gwarp = (blockIdx.x * blockDim.x + threadIdx.x) >> 5;
    int lane = threadIdx.x & 31;
    if (gwarp >= NN) return;
    int n = gwarp;
    int beg = g_off[n], end = g_off[n + 1];

    int h2 = lane >> 2;
    float sd2 = g_sd[n * 8 + h2];
    int c0 = (lane & 3) * 10;

    float acc[10];
#pragma unroll
    for (int j = 0; j < 10; j++) acc[j] = 0.f;
    float sumex = 0.f;

#pragma unroll 2
    for (int i = beg; i < end; ++i) {
        int s = g_srcc[i];
        float v = lrelu(g_ss[s * 8 + h2] + sd2);
        float ex = __expf(v);
        sumex += ex;
        const float* xr = &xg[(size_t)s * 320 + h2 * 40 + c0];
#pragma unroll
        for (int j = 0; j < 10; j += 2) {
            float2 t = *(const float2*)&xr[j];
            acc[j]     = fmaf(ex, t.x, acc[j]);
            acc[j + 1] = fmaf(ex, t.y, acc[j + 1]);
        }
    }
    float inv = 1.f / (sumex + 1e-16f);
#pragma unroll
    for (int j = 0; j < 10; ++j) {
        float v = acc[j] * inv;
        v += __shfl_xor_sync(0xffffffffu, v, 4);
        v += __shfl_xor_sync(0xffffffffu, v, 8);
        v += __shfl_xor_sync(0xffffffffu, v, 16);
        acc[j] = v;
    }
    if (lane < 4) {
#pragma unroll
        for (int j = 0; j < 10; ++j)
            out[(size_t)n * 40 + lane * 10 + j] = acc[j] * 0.125f + bias[lane * 10 + j];
    }
}

// ---------------- host ----------------
static inline dim3 ggrid(int M, int Cn) { return dim3((unsigned)((M + 127) / 128), (unsigned)(Cn / 64)); }

extern "C" void kernel_launch(void* const* d_in, const int* in_sizes, int n_in,
                              void* d_out, int out_size) {
    (void)in_sizes; (void)n_in; (void)out_size;
    const float* x     = (const float*)d_in[0];
    const int*   ei32  = (const int*)d_in[1];
    const float* ea    = (const float*)d_in[2];
    const float* e1_Ws = (const float*)d_in[3];
    const float* e1_Wd = (const float*)d_in[4];
    const float* e1_We = (const float*)d_in[5];
    const float* e1_b  = (const float*)d_in[6];
    const float* c1_Wv = (const float*)d_in[7];
    const float* c1_We = (const float*)d_in[8];
    const float* c1_as = (const float*)d_in[9];
    const float* c1_ad = (const float*)d_in[10];
    const float* c1_ae = (const float*)d_in[11];
    const float* e2_Ws = (const float*)d_in[12];
    const float* e2_Wd = (const float*)d_in[13];
    const float* e2_We = (const float*)d_in[14];
    const float* e2_b  = (const float*)d_in[15];
    const float* c2_Wv = (const float*)d_in[16];
    const float* c2_We = (const float*)d_in[17];
    const float* c2_as = (const float*)d_in[18];
    const float* c2_ad = (const float*)d_in[19];
    const float* c2_ae = (const float*)d_in[20];
    const float* g_Wp  = (const float*)d_in[21];
    const float* g_asP = (const float*)d_in[22];
    const float* g_adP = (const float*)d_in[23];
    const float* g_bP  = (const float*)d_in[24];
    float* out = (float*)d_out;

    void *p_efA, *p_efB, *p_xv, *p_h1, *p_h2, *p_xg;
    cudaGetSymbolAddress(&p_efA, g_efA);
    cudaGetSymbolAddress(&p_efB, g_efB);
    cudaGetSymbolAddress(&p_xv,  g_xv);
    cudaGetSymbolAddress(&p_h1,  g_h1);
    cudaGetSymbolAddress(&p_h2,  g_h2);
    cudaGetSymbolAddress(&p_xg,  g_xg);
    float* efA = (float*)p_efA; float* efB = (float*)p_efB;
    float* xv  = (float*)p_xv;  float* h1  = (float*)p_h1;
    float* h2  = (float*)p_h2;  float* xg  = (float*)p_xg;

    int nsgrid = (NN * 8 + 255) / 256 + 1;   // +1 block for wae

    prep_kernel<<<(EE + 255) / 256, 256>>>(ei32);                               // 1
    count_kernel<<<(EE + 255) / 256, 256>>>();                                  // 2
    scan_kernel<<<1, 1024>>>();                                                 // 3
    gemm3_kernel<<<dim3((NN + 127) / 128, 4), 256>>>(x, e1_Ws, e1_Wd, c1_Wv, NN, 128); // 4 <- ncu
    scatter_kernel<<<(EE + 255) / 256, 256>>>();                                // 5
    gemm_kernel<<<ggrid(EE, 64), 256>>>(ea, e1_We, efA, EE, 16, 64, 1, e1_b);   // 6
    node_scalar_kernel<<<nsgrid, 256>>>(xv, c1_as, c1_ad, 16, c1_We, c1_ae);    // 7
    egat_node_kernel<<<(NN + 7) / 8, 256>>>(xv, efA, c1_We, h1);                // 8

    gemm3_kernel<<<dim3((NN + 127) / 128, 4), 256>>>(h1, e2_Ws, e2_Wd, c2_Wv, NN, 256); // 9
    gemm_kernel<<<ggrid(EE, 64), 256>>>(efA, e2_We, efB, EE, 64, 64, 2, e2_b);  // 10
    node_scalar_kernel<<<nsgrid, 256>>>(xv, c2_as, c2_ad, 16, c2_We, c2_ae);    // 11
    egat_node_kernel<<<(NN + 7) / 8, 256>>>(xv, efB, c2_We, h2);                // 12

    gemm_kernel<<<ggrid(NN, 320), 256>>>(h2, g_Wp, xg, NN, 256, 320, 0, nullptr); // 13
    node_scalar_kernel<<<nsgrid - 1, 256>>>(xg, g_asP, g_adP, 40, nullptr, nullptr); // 14
    gat_node_kernel<<<(NN + 7) / 8, 256>>>(xg, g_bP, out);                      // 15
}